// round 11
// baseline (speedup 1.0000x reference)
#include <cuda_runtime.h>
#include <cuda_fp16.h>

#define BB 4
#define QQ 256
#define VV 2048
#define HH 512
#define UU 128

typedef unsigned int       u32;
typedef unsigned long long u64;
typedef unsigned short     u16;

// Scratch (device globals: allocation-free rule)
__device__ float g_pq[BB * QQ * UU];          // [B,Q,U] fp32
__device__ float g_pv[BB * VV * UU];          // [B,V,U] fp32
__device__ u16   g_ah[BB * QQ * VV];          // attn fp16 [B,Q,V]
__device__ u16   g_vth[BB * HH * VV];         // values^T fp16 [B,H,V]
__device__ u16   g_w1th[UU * HH];             // w1^T fp16 [U,H]
__device__ u16   g_w2th[UU * HH];             // w2^T fp16 [U,H]

__device__ __forceinline__ float ftanh(float x) {
    float y; asm("tanh.approx.f32 %0, %1;" : "=f"(y) : "f"(x)); return y;
}
__device__ __forceinline__ u32 smem_u32(const void* p) {
    u32 a;
    asm("{ .reg .u64 t; cvta.to.shared.u64 t, %1; cvt.u32.u64 %0, t; }"
        : "=r"(a) : "l"(p));
    return a;
}
__device__ __forceinline__ void ldsm4(u32& r0, u32& r1, u32& r2, u32& r3, u32 a) {
    asm volatile("ldmatrix.sync.aligned.m8n8.x4.shared.b16 {%0,%1,%2,%3}, [%4];"
                 : "=r"(r0), "=r"(r1), "=r"(r2), "=r"(r3) : "r"(a));
}
__device__ __forceinline__ void mma_fp(float* d, const u32* a, const u32* b) {
    asm volatile(
        "mma.sync.aligned.m16n8k16.row.col.f32.f16.f16.f32 "
        "{%0,%1,%2,%3}, {%4,%5,%6,%7}, {%8,%9}, {%0,%1,%2,%3};"
        : "+f"(d[0]), "+f"(d[1]), "+f"(d[2]), "+f"(d[3])
        : "r"(a[0]), "r"(a[1]), "r"(a[2]), "r"(a[3]), "r"(b[0]), "r"(b[1]));
}
__device__ __forceinline__ u32 packh2(float a, float b) {
    u32 r;
    asm("cvt.rn.f16x2.f32 %0, %2, %1;" : "=r"(r) : "f"(a), "f"(b));  // lo=a, hi=b
    return r;
}

// ---------------------------------------------------------------------------
// Kernel 0: convert.
//   blocks [0,1024):    values 64x64 tiles -> g_vth (transposed, fp16)
//   blocks [1024,1056): w1/w2 64x64 tiles -> w^T fp16
// ---------------------------------------------------------------------------
__global__ __launch_bounds__(256) void convert_kernel(
    const float* __restrict__ values,
    const float* __restrict__ w1, const float* __restrict__ w2)
{
    __shared__ float ts[64 * 65];
    const int bx = blockIdx.x, tid = threadIdx.x;

    if (bx < 1024) {
        const int b = bx >> 8, t = bx & 255;
        const int v0 = (t & 31) * 64, h0 = (t >> 5) * 64;
        const int r = tid >> 2, c0 = tid & 3;
#pragma unroll
        for (int it = 0; it < 4; it++) {
            int c4 = c0 * 4 + it;
            float4 f = ((const float4*)(values + (size_t)(b * VV + v0 + r) * HH + h0))[c4];
            ts[r * 65 + c4 * 4 + 0] = f.x;
            ts[r * 65 + c4 * 4 + 1] = f.y;
            ts[r * 65 + c4 * 4 + 2] = f.z;
            ts[r * 65 + c4 * 4 + 3] = f.w;
        }
        __syncthreads();
        const int hr = tid >> 2, s0 = tid & 3;
#pragma unroll
        for (int it = 0; it < 4; it++) {
            int vs = s0 * 4 + it;
            float f0 = ts[(vs * 4 + 0) * 65 + hr];
            float f1 = ts[(vs * 4 + 1) * 65 + hr];
            float f2 = ts[(vs * 4 + 2) * 65 + hr];
            float f3 = ts[(vs * 4 + 3) * 65 + hr];
            size_t off = (size_t)(b * HH + h0 + hr) * VV + v0 + vs * 4;
            *(uint2*)(g_vth + off) = make_uint2(packh2(f0, f1), packh2(f2, f3));
        }
    } else {
        const int wb = bx - 1024;
        const float* W = (wb < 16) ? w1 : w2;
        u16* dh = (wb < 16) ? g_w1th : g_w2th;
        const int t = wb & 15;
        const int h0 = (t & 7) * 64, u0 = (t >> 3) * 64;
        const int r = tid >> 2, c0 = tid & 3;
#pragma unroll
        for (int it = 0; it < 4; it++) {
            int c4 = c0 * 4 + it;
            float4 f = ((const float4*)(W + (size_t)(h0 + r) * UU + u0))[c4];
            ts[r * 65 + c4 * 4 + 0] = f.x;
            ts[r * 65 + c4 * 4 + 1] = f.y;
            ts[r * 65 + c4 * 4 + 2] = f.z;
            ts[r * 65 + c4 * 4 + 3] = f.w;
        }
        __syncthreads();
        const int ur = tid >> 2, s0 = tid & 3;
#pragma unroll
        for (int it = 0; it < 4; it++) {
            int hs = s0 * 4 + it;
            float f0 = ts[(hs * 4 + 0) * 65 + ur];
            float f1 = ts[(hs * 4 + 1) * 65 + ur];
            float f2 = ts[(hs * 4 + 2) * 65 + ur];
            float f3 = ts[(hs * 4 + 3) * 65 + ur];
            size_t off = (size_t)(u0 + ur) * HH + h0 + hs * 4;
            *(uint2*)(dh + off) = make_uint2(packh2(f0, f1), packh2(f2, f3));
        }
    }
}

// ---------------------------------------------------------------------------
// Kernel A: projections via mma.sync fp16, SINGLE product.
//   blocks [0,128):  pv = values @ w2;  blocks [128,144): pq = queries @ w1
// CTA tile M=64 x N=128(=U), BK=64, 8 chunks. 8 warps = 2(m)x4(n), warp 32x32.
// A loaded fp32, converted fp16 inline. B = w^T fp16. B loaded via ldsm4
// (one x4 covers 16 n-rows x 16 k).
// ---------------------------------------------------------------------------
__global__ __launch_bounds__(256) void proj_tc_kernel(
    const float* __restrict__ queries, const float* __restrict__ values)
{
    __shared__ __align__(16) u16 sA[64 * 72];
    __shared__ __align__(16) u16 sB[128 * 72];

    const int tid = threadIdx.x;
    const int wid = tid >> 5;
    const int lane = tid & 31;
    const int bx = blockIdx.x;

    const float* Afp; const u16* Bw; float* C; int m0;
    if (bx < 128) { Afp = values;  Bw = g_w2th; C = g_pv; m0 = bx * 64; }
    else          { Afp = queries; Bw = g_w1th; C = g_pq; m0 = (bx - 128) * 64; }

    const int wm0 = (wid >> 2) * 32;   // 0,32
    const int wn0 = (wid & 3) * 32;    // 0,32,64,96

    const int ar = tid >> 2, ac4 = tid & 3;   // A: row, 16 floats
    const int br = tid >> 1, bg = tid & 1;    // B: row, 4 granules

    const float4* gA4 = (const float4*)(Afp + (size_t)m0 * HH);
    const uint4* gB4 = (const uint4*)Bw;
    const int RWA = HH / 4;   // 128
    const int RWB = HH / 8;   // 64

    float dacc[2][4][4];
#pragma unroll
    for (int i = 0; i < 2; i++)
#pragma unroll
        for (int j = 0; j < 4; j++)
#pragma unroll
            for (int c = 0; c < 4; c++) dacc[i][j][c] = 0.f;

    float4 pA[4];
    uint4 pB[4];
#pragma unroll
    for (int it = 0; it < 4; it++)
        pA[it] = gA4[(size_t)ar * RWA + ac4 * 4 + it];
#pragma unroll
    for (int j = 0; j < 4; j++)
        pB[j] = gB4[(size_t)br * RWB + bg * 4 + j];

    const u32 bA = smem_u32(sA), bB = smem_u32(sB);

    // ldmatrix addressing
    const int arow = wm0 + (lane & 15);
    const u32 aoff = (u32)(arow * 9 + (lane >> 4)) * 16;
    // B x4 grouped: rows wn0 + p*16 + ((lane>>4)<<3) + (lane&7); gran (lane>>3)&1
    const int brow_base = ((lane >> 4) << 3) + (lane & 7);
    const int bgr = (lane >> 3) & 1;

    const int NCH = HH / 64;   // 8

    for (int c = 0; c < NCH; c++) {
        // store chunk c
#pragma unroll
        for (int it = 0; it < 4; it++) {
            u32 h01 = packh2(pA[it].x, pA[it].y);
            u32 h23 = packh2(pA[it].z, pA[it].w);
            u32 s = (u32)(ar * 72 + (ac4 * 4 + it) * 4);
            *(uint2*)(sA + s) = make_uint2(h01, h23);
        }
#pragma unroll
        for (int j = 0; j < 4; j++) {
            u32 s = (u32)(br * 72 + (bg * 4 + j) * 8);
            *(uint4*)(sB + s) = pB[j];
        }
        if (c + 1 < NCH) {
            int fa = (c + 1) * 16, fb = (c + 1) * 8;
#pragma unroll
            for (int it = 0; it < 4; it++)
                pA[it] = gA4[(size_t)ar * RWA + fa + ac4 * 4 + it];
#pragma unroll
            for (int j = 0; j < 4; j++)
                pB[j] = gB4[(size_t)br * RWB + fb + bg * 4 + j];
        }
        __syncthreads();

#pragma unroll
        for (int kb = 0; kb < 4; kb++) {
            u32 a[2][4], bb[4][2];
#pragma unroll
            for (int mf = 0; mf < 2; mf++) {
                u32 ad = (u32)((mf * 16) * 9) * 16 + aoff + (u32)(kb * 2) * 16;
                ldsm4(a[mf][0], a[mf][1], a[mf][2], a[mf][3], bA + ad);
            }
#pragma unroll
            for (int p = 0; p < 2; p++) {
                int row = wn0 + p * 16 + brow_base;
                u32 bd = (u32)(row * 9 + kb * 2 + bgr) * 16;
                u32 r0, r1, r2, r3;
                ldsm4(r0, r1, r2, r3, bB + bd);
                bb[p * 2 + 0][0] = r0; bb[p * 2 + 0][1] = r1;
                bb[p * 2 + 1][0] = r2; bb[p * 2 + 1][1] = r3;
            }
#pragma unroll
            for (int mf = 0; mf < 2; mf++)
#pragma unroll
                for (int nf = 0; nf < 4; nf++)
                    mma_fp(dacc[mf][nf], a[mf], bb[nf]);
        }
        __syncthreads();
    }

    const int g = lane >> 2;
    const int t = lane & 3;
#pragma unroll
    for (int mf = 0; mf < 2; mf++)
#pragma unroll
        for (int nf = 0; nf < 4; nf++) {
            int row = m0 + wm0 + mf * 16 + g;
            int col = wn0 + nf * 8 + t * 2;
            float2 v0, v1;
            v0.x = dacc[mf][nf][0]; v0.y = dacc[mf][nf][1];
            v1.x = dacc[mf][nf][2]; v1.y = dacc[mf][nf][3];
            *(float2*)(C + (size_t)row * UU + col) = v0;
            *(float2*)(C + (size_t)(row + 8) * UU + col) = v1;
        }
}

// ---------------------------------------------------------------------------
// Kernel B: scores + softmax -> attn (fp16). Persistent 148 CTAs.
// fp32 tanh (MUFU floor). Identical to the proven R9 kernel.
// ---------------------------------------------------------------------------
#define SCORE_GRID 148
#define CPB 37
#define NQMAX 7

__global__ __launch_bounds__(256) void score_kernel(const float* __restrict__ vvec)
{
    extern __shared__ float4 sm4[];
    float4* pvs4 = sm4;                       // 32*33 f4
    float4* pqs4 = sm4 + 1056;                // 224 f4
    float4* vs4  = sm4 + 1056 + 224;          // 32 f4
    float*  scores = (float*)(sm4 + 1312);    // 7*2048 floats
    float*  sp     = scores + NQMAX * VV;     // 1792 floats

    const int tid = threadIdx.x;
    const int b     = blockIdx.x / CPB;
    const int local = blockIdx.x % CPB;
    const int nq = (local < 34) ? 7 : 6;
    const int q0 = (local < 34) ? local * 7 : 238 + (local - 34) * 6;

    {
        const float4* pqg4 = (const float4*)(g_pq + (size_t)(b * QQ + q0) * UU);
        if (tid < nq * 32) pqs4[tid] = pqg4[tid];
        if (tid < 32) vs4[tid] = ((const float4*)vvec)[tid];
    }

    const float4* pv4 = (const float4*)g_pv;
    const int r  = tid & 31;
    const int ug = tid >> 5;
    const int lrr = tid >> 5;
    const int lc  = tid & 31;

    float4 pf[4];
#pragma unroll
    for (int i = 0; i < 4; i++)
        pf[i] = pv4[(size_t)(b * VV + lrr + i * 8) * 32 + lc];

    __syncthreads();

    float4 vw[4];
#pragma unroll
    for (int u4 = 0; u4 < 4; u4++) vw[u4] = vs4[ug * 4 + u4];

    for (int vt = 0; vt < VV; vt += 32) {
#pragma unroll
        for (int i = 0; i < 4; i++)
            pvs4[(lrr + i * 8) * 33 + lc] = pf[i];
        if (vt + 32 < VV) {
#pragma unroll
            for (int i = 0; i < 4; i++)
                pf[i] = pv4[(size_t)(b * VV + vt + 32 + lrr + i * 8) * 32 + lc];
        }
        __syncthreads();

        float acc[NQMAX];
#pragma unroll
        for (int q = 0; q < NQMAX; q++) acc[q] = 0.f;

        const float4* prow = pvs4 + r * 33 + ug * 4;
#pragma unroll
        for (int u4 = 0; u4 < 4; u4++) {
            float4 p = prow[u4];
            float4 w = vw[u4];
#pragma unroll
            for (int q = 0; q < NQMAX; q++) {
                float4 qv = pqs4[q * 32 + ug * 4 + u4];
                acc[q] += ftanh(qv.x + p.x) * w.x;
                acc[q] += ftanh(qv.y + p.y) * w.y;
                acc[q] += ftanh(qv.z + p.z) * w.z;
                acc[q] += ftanh(qv.w + p.w) * w.w;
            }
        }
#pragma unroll
        for (int q = 0; q < NQMAX; q++) sp[q * 256 + tid] = acc[q];
        __syncthreads();

        if (tid < 224) {
            int q = tid >> 5, rr = tid & 31;
            float s = 0.f;
#pragma unroll
            for (int u = 0; u < 8; u++) s += sp[q * 256 + u * 32 + rr];
            scores[q * VV + vt + rr] = s;
        }
        __syncthreads();
    }

    float* red = sp;
    for (int qi = 0; qi < nq; qi++) {
        float* sc = scores + qi * VV;

        float m = -1e30f;
        for (int i = tid; i < VV; i += 256) m = fmaxf(m, sc[i]);
        red[tid] = m;
        __syncthreads();
        for (int s = 128; s > 0; s >>= 1) {
            if (tid < s) red[tid] = fmaxf(red[tid], red[tid + s]);
            __syncthreads();
        }
        m = red[0];
        __syncthreads();

        float lsum = 0.f;
        for (int i = tid; i < VV; i += 256) {
            float e = __expf(sc[i] - m);
            sc[i] = e;
            lsum += e;
        }
        red[tid] = lsum;
        __syncthreads();
        for (int s = 128; s > 0; s >>= 1) {
            if (tid < s) red[tid] += red[tid + s];
            __syncthreads();
        }
        float inv = 1.f / red[0];
        __syncthreads();

        size_t rowoff = (size_t)(b * QQ + q0 + qi) * VV;
        const float4* sc4 = (const float4*)sc;
        for (int i = tid; i < VV / 4; i += 256) {
            float4 e = sc4[i];
            *(uint2*)(g_ah + rowoff + i * 4) =
                make_uint2(packh2(e.x * inv, e.y * inv), packh2(e.z * inv, e.w * inv));
        }
        __syncthreads();
    }
}

// ---------------------------------------------------------------------------
// Kernel C: out[b] = attn[b] @ values[b] via mma.sync fp16, single product.
// CTA tile M=32 x N=64, BK=128, 16 chunks. 8 warps = 2(m)x4(n); warp 16x16.
// B loaded via grouped ldsm4. Row stride 17 granules (136 u16).
// Grid (8, 8, 4) = 256 CTAs, ~25.5KB SMEM -> 2 CTAs/SM.
// ---------------------------------------------------------------------------
__global__ __launch_bounds__(256) void av_mma_kernel(float* __restrict__ out)
{
    __shared__ __align__(16) u16 sA[32 * 136];
    __shared__ __align__(16) u16 sB[64 * 136];

    const int tid = threadIdx.x;
    const int wid = tid >> 5;
    const int lane = tid & 31;

    const int b  = blockIdx.z;
    const int m0 = blockIdx.y * 32;
    const int n0 = blockIdx.x * 64;

    const int wm0 = (wid >> 2) * 16;   // 0,16
    const int wn0 = (wid & 3) * 16;    // 0,16,32,48

    // global load coords: A 32 rows x 16 granules (2/thread), B 64x16 (4/thread)
    const int ar = tid >> 3, ag = (tid & 7) * 2;
    const int br = tid >> 2, bg = (tid & 3) * 4;

    const uint4* gA = (const uint4*)(g_ah + (size_t)(b * QQ + m0) * VV);
    const uint4* gB = (const uint4*)(g_vth + (size_t)(b * HH + n0) * VV);
    const int RW = VV / 8;   // 256 granules per row

    float dacc[2][4];
#pragma unroll
    for (int j = 0; j < 2; j++)
#pragma unroll
        for (int c = 0; c < 4; c++) dacc[j][c] = 0.f;

    uint4 pA[2], pB[4];
#pragma unroll
    for (int j = 0; j < 2; j++)
        pA[j] = gA[(size_t)ar * RW + ag + j];
#pragma unroll
    for (int j = 0; j < 4; j++)
        pB[j] = gB[(size_t)br * RW + bg + j];

    const u32 bA = smem_u32(sA), bB = smem_u32(sB);

    // ldmatrix addressing
    const int arow = wm0 + (lane & 15);
    const int agr  = lane >> 4;
    const int brow = wn0 + ((lane >> 4) << 3) + (lane & 7);
    const int bgr  = (lane >> 3) & 1;

    const int NCH = VV / 128;   // 16

    for (int c = 0; c < NCH; c++) {
        // store chunk c
#pragma unroll
        for (int j = 0; j < 2; j++) {
            u32 s = (u32)(ar * 17 + ag + j) * 8;
            *(uint4*)(sA + s) = pA[j];
        }
#pragma unroll
        for (int j = 0; j < 4; j++) {
            u32 s = (u32)(br * 17 + bg + j) * 8;
            *(uint4*)(sB + s) = pB[j];
        }
        // prefetch chunk c+1
        if (c + 1 < NCH) {
            int g0 = (c + 1) * 16;
#pragma unroll
            for (int j = 0; j < 2; j++)
                pA[j] = gA[(size_t)ar * RW + g0 + ag + j];
#pragma unroll
            for (int j = 0; j < 4; j++)
                pB[j] = gB[(size_t)br * RW + g0 + bg + j];
        }
        __syncthreads();

#pragma unroll
        for (int kb = 0; kb < 8; kb++) {
            u32 a[4], r0, r1, r2, r3;
            u32 ad = (u32)(arow * 17 + kb * 2 + agr) * 16;
            ldsm4(a[0], a[1], a[2], a[3], bA + ad);
            u32 bd = (u32)(brow * 17 + kb * 2 + bgr) * 16;
            ldsm4(r0, r1, r2, r3, bB + bd);
            u32 bb0[2] = {r0, r1};
            u32 bb1[2] = {r2, r3};
            mma_fp(dacc[0], a, bb0);
            mma_fp(dacc[1], a, bb1);
        }
        __syncthreads();
    }

    const int g = lane >> 2;
    const int t = lane & 3;
#pragma unroll
    for (int nf = 0; nf < 2; nf++) {
        int row = m0 + wm0 + g;
        int col = n0 + wn0 + nf * 8 + t * 2;
        float2 v0, v1;
        v0.x = dacc[nf][0]; v0.y = dacc[nf][1];
        v1.x = dacc[nf][2]; v1.y = dacc[nf][3];
        *(float2*)(out + (size_t)(b * QQ + row) * HH + col) = v0;
        *(float2*)(out + (size_t)(b * QQ + row + 8) * HH + col) = v1;
    }
}

// ---------------------------------------------------------------------------
extern "C" void kernel_launch(void* const* d_in, const int* in_sizes, int n_in,
                              void* d_out, int out_size)
{
    const float* queries = (const float*)d_in[0];
    const float* values  = (const float*)d_in[1];
    const float* w1      = (const float*)d_in[2];
    const float* w2      = (const float*)d_in[3];
    const float* vvec    = (const float*)d_in[4];
    float* out = (float*)d_out;

    const int smemB = 1312 * 16 + (NQMAX * VV + 1792) * 4;  // 85,504 B
    cudaFuncSetAttribute(score_kernel,
                         cudaFuncAttributeMaxDynamicSharedMemorySize, smemB);

    convert_kernel<<<1056, 256>>>(values, w1, w2);
    proj_tc_kernel<<<144, 256>>>(queries, values);
    score_kernel<<<SCORE_GRID, 256, smemB>>>(vvec);
    av_mma_kernel<<<dim3(HH / 64, QQ / 32, BB), 256>>>(out);
}

// round 12
// speedup vs baseline: 1.0508x; 1.0508x over previous
#include <cuda_runtime.h>
#include <cuda_fp16.h>

#define BB 4
#define QQ 256
#define VV 2048
#define HH 512
#define UU 128

typedef unsigned int       u32;
typedef unsigned long long u64;
typedef unsigned short     u16;

// Scratch (device globals: allocation-free rule)
__device__ float g_pq[BB * QQ * UU];          // [B,Q,U] fp32
__device__ float g_pv[BB * VV * UU];          // [B,V,U] fp32
__device__ u16   g_ah[BB * QQ * VV];          // attn fp16 [B,Q,V]
__device__ u16   g_vth[BB * HH * VV];         // values^T fp16 [B,H,V]
__device__ u16   g_w1th[UU * HH];             // w1^T fp16 [U,H]
__device__ u16   g_w2th[UU * HH];             // w2^T fp16 [U,H]

__device__ __forceinline__ u32 smem_u32(const void* p) {
    u32 a;
    asm("{ .reg .u64 t; cvta.to.shared.u64 t, %1; cvt.u32.u64 %0, t; }"
        : "=r"(a) : "l"(p));
    return a;
}
__device__ __forceinline__ void ldsm4(u32& r0, u32& r1, u32& r2, u32& r3, u32 a) {
    asm volatile("ldmatrix.sync.aligned.m8n8.x4.shared.b16 {%0,%1,%2,%3}, [%4];"
                 : "=r"(r0), "=r"(r1), "=r"(r2), "=r"(r3) : "r"(a));
}
__device__ __forceinline__ void ldsm2(u32& r0, u32& r1, u32 a) {
    asm volatile("ldmatrix.sync.aligned.m8n8.x2.shared.b16 {%0,%1}, [%2];"
                 : "=r"(r0), "=r"(r1) : "r"(a));
}
__device__ __forceinline__ void mma_fp(float* d, const u32* a, const u32* b) {
    asm volatile(
        "mma.sync.aligned.m16n8k16.row.col.f32.f16.f16.f32 "
        "{%0,%1,%2,%3}, {%4,%5,%6,%7}, {%8,%9}, {%0,%1,%2,%3};"
        : "+f"(d[0]), "+f"(d[1]), "+f"(d[2]), "+f"(d[3])
        : "r"(a[0]), "r"(a[1]), "r"(a[2]), "r"(a[3]), "r"(b[0]), "r"(b[1]));
}
__device__ __forceinline__ u32 packh2(float a, float b) {
    u32 r;
    asm("cvt.rn.f16x2.f32 %0, %2, %1;" : "=r"(r) : "f"(a), "f"(b));  // lo=a, hi=b
    return r;
}
__device__ __forceinline__ u32 hadd2(u32 a, u32 b) {
    u32 r; asm("add.rn.f16x2 %0, %1, %2;" : "=r"(r) : "r"(a), "r"(b)); return r;
}
__device__ __forceinline__ u32 hfma2(u32 a, u32 b, u32 c) {
    u32 r; asm("fma.rn.f16x2 %0, %1, %2, %3;" : "=r"(r) : "r"(a), "r"(b), "r"(c)); return r;
}
__device__ __forceinline__ u32 tanh2(u32 x) {
    u32 r; asm("tanh.approx.f16x2 %0, %1;" : "=r"(r) : "r"(x)); return r;
}
__device__ __forceinline__ float2 h2f2(u32 h) {
    __half2 hv = *reinterpret_cast<__half2*>(&h);
    return __half22float2(hv);
}

// ---------------------------------------------------------------------------
// Kernel 0: w1/w2 transpose -> fp16 (32 blocks; must precede proj).
// ---------------------------------------------------------------------------
__global__ __launch_bounds__(256) void wconv_kernel(
    const float* __restrict__ w1, const float* __restrict__ w2)
{
    __shared__ float ts[64 * 65];
    const int wb = blockIdx.x, tid = threadIdx.x;
    const float* W = (wb < 16) ? w1 : w2;
    u16* dh = (wb < 16) ? g_w1th : g_w2th;
    const int t = wb & 15;
    const int h0 = (t & 7) * 64, u0 = (t >> 3) * 64;
    const int r = tid >> 2, c0 = tid & 3;
#pragma unroll
    for (int it = 0; it < 4; it++) {
        int c4 = c0 * 4 + it;
        float4 f = ((const float4*)(W + (size_t)(h0 + r) * UU + u0))[c4];
        ts[r * 65 + c4 * 4 + 0] = f.x;
        ts[r * 65 + c4 * 4 + 1] = f.y;
        ts[r * 65 + c4 * 4 + 2] = f.z;
        ts[r * 65 + c4 * 4 + 3] = f.w;
    }
    __syncthreads();
    const int ur = tid >> 2, s0 = tid & 3;
#pragma unroll
    for (int it = 0; it < 4; it++) {
        int hs = s0 * 4 + it;
        float f0 = ts[(hs * 4 + 0) * 65 + ur];
        float f1 = ts[(hs * 4 + 1) * 65 + ur];
        float f2 = ts[(hs * 4 + 2) * 65 + ur];
        float f3 = ts[(hs * 4 + 3) * 65 + ur];
        size_t off = (size_t)(u0 + ur) * HH + h0 + hs * 4;
        *(uint2*)(dh + off) = make_uint2(packh2(f0, f1), packh2(f2, f3));
    }
}

// ---------------------------------------------------------------------------
// Kernel A (FUSED): blocks [0,144) = projections (mma.sync fp16, single
// product); blocks [144,1200) = values 64x64 tiles -> g_vth (transposed fp16,
// memory-bound, co-resident with proj CTAs -> hidden under proj).
// proj: CTA tile M=64 x N=128(=U), BK=64, 8 chunks. 8 warps = 2(m)x4(n).
// ---------------------------------------------------------------------------
__global__ __launch_bounds__(256) void proj_conv_kernel(
    const float* __restrict__ queries, const float* __restrict__ values)
{
    __shared__ __align__(16) char sm[27648];
    const int tid = threadIdx.x;
    const int bx = blockIdx.x;

    if (bx >= 144) {
        // ---- values^T conversion branch ----
        float* ts = (float*)sm;               // 64*65 floats = 16,640 B
        const int vb = bx - 144;
        const int b = vb >> 8, t = vb & 255;
        const int v0 = (t & 31) * 64, h0 = (t >> 5) * 64;
        const int r = tid >> 2, c0 = tid & 3;
#pragma unroll
        for (int it = 0; it < 4; it++) {
            int c4 = c0 * 4 + it;
            float4 f = ((const float4*)(values + (size_t)(b * VV + v0 + r) * HH + h0))[c4];
            ts[r * 65 + c4 * 4 + 0] = f.x;
            ts[r * 65 + c4 * 4 + 1] = f.y;
            ts[r * 65 + c4 * 4 + 2] = f.z;
            ts[r * 65 + c4 * 4 + 3] = f.w;
        }
        __syncthreads();
        const int hr = tid >> 2, s0 = tid & 3;
#pragma unroll
        for (int it = 0; it < 4; it++) {
            int vs = s0 * 4 + it;
            float f0 = ts[(vs * 4 + 0) * 65 + hr];
            float f1 = ts[(vs * 4 + 1) * 65 + hr];
            float f2 = ts[(vs * 4 + 2) * 65 + hr];
            float f3 = ts[(vs * 4 + 3) * 65 + hr];
            size_t off = (size_t)(b * HH + h0 + hr) * VV + v0 + vs * 4;
            *(uint2*)(g_vth + off) = make_uint2(packh2(f0, f1), packh2(f2, f3));
        }
        return;
    }

    // ---- projection branch ----
    u16* sA = (u16*)sm;                 //  64*72 u16 =  9,216 B
    u16* sB = (u16*)(sm + 9216);        // 128*72 u16 = 18,432 B

    const int wid = tid >> 5;
    const int lane = tid & 31;

    const float* Afp; const u16* Bw; float* C; int m0;
    if (bx < 128) { Afp = values;  Bw = g_w2th; C = g_pv; m0 = bx * 64; }
    else          { Afp = queries; Bw = g_w1th; C = g_pq; m0 = (bx - 128) * 64; }

    const int wm0 = (wid >> 2) * 32;   // 0,32
    const int wn0 = (wid & 3) * 32;    // 0,32,64,96

    const int ar = tid >> 2, ac4 = tid & 3;   // A: row, 16 floats
    const int br = tid >> 1, bg = tid & 1;    // B: row, 4 granules

    const float4* gA4 = (const float4*)(Afp + (size_t)m0 * HH);
    const uint4* gB4 = (const uint4*)Bw;
    const int RWA = HH / 4;   // 128
    const int RWB = HH / 8;   // 64

    float dacc[2][4][4];
#pragma unroll
    for (int i = 0; i < 2; i++)
#pragma unroll
        for (int j = 0; j < 4; j++)
#pragma unroll
            for (int c = 0; c < 4; c++) dacc[i][j][c] = 0.f;

    float4 pA[4];
    uint4 pB[4];
#pragma unroll
    for (int it = 0; it < 4; it++)
        pA[it] = gA4[(size_t)ar * RWA + ac4 * 4 + it];
#pragma unroll
    for (int j = 0; j < 4; j++)
        pB[j] = gB4[(size_t)br * RWB + bg * 4 + j];

    const u32 bA = smem_u32(sA), bB = smem_u32(sB);

    const int arow = wm0 + (lane & 15);
    const u32 aoff = (u32)(arow * 9 + (lane >> 4)) * 16;
    const int brow_base = ((lane >> 4) << 3) + (lane & 7);
    const int bgr = (lane >> 3) & 1;

    const int NCH = HH / 64;   // 8

    for (int c = 0; c < NCH; c++) {
#pragma unroll
        for (int it = 0; it < 4; it++) {
            u32 h01 = packh2(pA[it].x, pA[it].y);
            u32 h23 = packh2(pA[it].z, pA[it].w);
            u32 s = (u32)(ar * 72 + (ac4 * 4 + it) * 4);
            *(uint2*)(sA + s) = make_uint2(h01, h23);
        }
#pragma unroll
        for (int j = 0; j < 4; j++) {
            u32 s = (u32)(br * 72 + (bg * 4 + j) * 8);
            *(uint4*)(sB + s) = pB[j];
        }
        if (c + 1 < NCH) {
            int fa = (c + 1) * 16, fb = (c + 1) * 8;
#pragma unroll
            for (int it = 0; it < 4; it++)
                pA[it] = gA4[(size_t)ar * RWA + fa + ac4 * 4 + it];
#pragma unroll
            for (int j = 0; j < 4; j++)
                pB[j] = gB4[(size_t)br * RWB + fb + bg * 4 + j];
        }
        __syncthreads();

#pragma unroll
        for (int kb = 0; kb < 4; kb++) {
            u32 a[2][4], bb[4][2];
#pragma unroll
            for (int mf = 0; mf < 2; mf++) {
                u32 ad = (u32)((mf * 16) * 9) * 16 + aoff + (u32)(kb * 2) * 16;
                ldsm4(a[mf][0], a[mf][1], a[mf][2], a[mf][3], bA + ad);
            }
#pragma unroll
            for (int p = 0; p < 2; p++) {
                int row = wn0 + p * 16 + brow_base;
                u32 bd = (u32)(row * 9 + kb * 2 + bgr) * 16;
                u32 r0, r1, r2, r3;
                ldsm4(r0, r1, r2, r3, bB + bd);
                bb[p * 2 + 0][0] = r0; bb[p * 2 + 0][1] = r1;
                bb[p * 2 + 1][0] = r2; bb[p * 2 + 1][1] = r3;
            }
#pragma unroll
            for (int mf = 0; mf < 2; mf++)
#pragma unroll
                for (int nf = 0; nf < 4; nf++)
                    mma_fp(dacc[mf][nf], a[mf], bb[nf]);
        }
        __syncthreads();
    }

    const int g = lane >> 2;
    const int t = lane & 3;
#pragma unroll
    for (int mf = 0; mf < 2; mf++)
#pragma unroll
        for (int nf = 0; nf < 4; nf++) {
            int row = m0 + wm0 + mf * 16 + g;
            int col = wn0 + nf * 8 + t * 2;
            float2 v0, v1;
            v0.x = dacc[mf][nf][0]; v0.y = dacc[mf][nf][1];
            v1.x = dacc[mf][nf][2]; v1.y = dacc[mf][nf][3];
            *(float2*)(C + (size_t)row * UU + col) = v0;
            *(float2*)(C + (size_t)(row + 8) * UU + col) = v1;
        }
}

// ---------------------------------------------------------------------------
// Kernel B: scores + softmax -> attn (fp16). Persistent 148 CTAs.
// Packed f16x2 pipeline: hadd2 -> tanh2 (1 MUFU / 2 elems) -> hfma2 (packed
// fp16 accumulate over 8 pairs), fp32 handoff per 16-term thread partial.
// Dynamic SMEM = 74,880 B.
// ---------------------------------------------------------------------------
#define SCORE_GRID 148
#define CPB 37
#define NQMAX 7

__global__ __launch_bounds__(256) void score_kernel(const float* __restrict__ vvec)
{
    extern __shared__ u32 smu[];
    u32*   pvs2 = smu;                         // 32*65 = 2080 u32
    u32*   pqs2 = smu + 2080;                  // 7*64 = 448 u32
    u32*   vs2  = smu + 2528;                  // 64 u32 (v as f16x2)
    float* scores = (float*)(smu + 2592);      // 7*2048 floats
    float* sp     = scores + NQMAX * VV;       // 1792 floats

    const int tid = threadIdx.x;
    const int b     = blockIdx.x / CPB;
    const int local = blockIdx.x % CPB;
    const int nq = (local < 34) ? 7 : 6;
    const int q0 = (local < 34) ? local * 7 : 238 + (local - 34) * 6;

    // stage pq (f16x2) and v (f16x2)
    if (tid < nq * 32) {
        int q = tid >> 5, j = tid & 31;
        float4 f = ((const float4*)(g_pq + (size_t)(b * QQ + q0 + q) * UU))[j];
        pqs2[q * 64 + 2 * j]     = packh2(f.x, f.y);
        pqs2[q * 64 + 2 * j + 1] = packh2(f.z, f.w);
    }
    if (tid < 32) {
        float4 wv = ((const float4*)vvec)[tid];
        vs2[2 * tid]     = packh2(wv.x, wv.y);
        vs2[2 * tid + 1] = packh2(wv.z, wv.w);
    }

    const float4* pv4 = (const float4*)g_pv;
    const int r  = tid & 31;
    const int ug = tid >> 5;
    const int lrr = tid >> 5;
    const int lc  = tid & 31;

    float4 pf[4];
#pragma unroll
    for (int i = 0; i < 4; i++)
        pf[i] = pv4[(size_t)(b * VV + lrr + i * 8) * 32 + lc];

    __syncthreads();

    u32 vw2[8];
#pragma unroll
    for (int u2 = 0; u2 < 8; u2++) vw2[u2] = vs2[ug * 8 + u2];

    for (int vt = 0; vt < VV; vt += 32) {
        // stage pv tile as f16x2 (row stride 65 u32)
#pragma unroll
        for (int i = 0; i < 4; i++) {
            int row = lrr + i * 8;
            pvs2[row * 65 + 2 * lc]     = packh2(pf[i].x, pf[i].y);
            pvs2[row * 65 + 2 * lc + 1] = packh2(pf[i].z, pf[i].w);
        }
        if (vt + 32 < VV) {
#pragma unroll
            for (int i = 0; i < 4; i++)
                pf[i] = pv4[(size_t)(b * VV + vt + 32 + lrr + i * 8) * 32 + lc];
        }
        __syncthreads();

        u32 acc2[NQMAX];
#pragma unroll
        for (int q = 0; q < NQMAX; q++) acc2[q] = 0u;

        const u32* prow = pvs2 + r * 65 + ug * 8;
#pragma unroll
        for (int u2 = 0; u2 < 8; u2++) {
            u32 p2 = prow[u2];
            u32 w2 = vw2[u2];
#pragma unroll
            for (int q = 0; q < NQMAX; q++) {
                u32 q2 = pqs2[q * 64 + ug * 8 + u2];   // warp-uniform broadcast
                acc2[q] = hfma2(tanh2(hadd2(q2, p2)), w2, acc2[q]);
            }
        }
#pragma unroll
        for (int q = 0; q < NQMAX; q++) {
            float2 t = h2f2(acc2[q]);
            sp[q * 256 + tid] = t.x + t.y;
        }
        __syncthreads();

        if (tid < 224) {
            int q = tid >> 5, rr = tid & 31;
            float s = 0.f;
#pragma unroll
            for (int u = 0; u < 8; u++) s += sp[q * 256 + u * 32 + rr];
            scores[q * VV + vt + rr] = s;
        }
        __syncthreads();
    }

    float* red = sp;
    for (int qi = 0; qi < nq; qi++) {
        float* sc = scores + qi * VV;

        float m = -1e30f;
        for (int i = tid; i < VV; i += 256) m = fmaxf(m, sc[i]);
        red[tid] = m;
        __syncthreads();
        for (int s = 128; s > 0; s >>= 1) {
            if (tid < s) red[tid] = fmaxf(red[tid], red[tid + s]);
            __syncthreads();
        }
        m = red[0];
        __syncthreads();

        float lsum = 0.f;
        for (int i = tid; i < VV; i += 256) {
            float e = __expf(sc[i] - m);
            sc[i] = e;
            lsum += e;
        }
        red[tid] = lsum;
        __syncthreads();
        for (int s = 128; s > 0; s >>= 1) {
            if (tid < s) red[tid] += red[tid + s];
            __syncthreads();
        }
        float inv = 1.f / red[0];
        __syncthreads();

        size_t rowoff = (size_t)(b * QQ + q0 + qi) * VV;
        const float4* sc4 = (const float4*)sc;
        for (int i = tid; i < VV / 4; i += 256) {
            float4 e = sc4[i];
            *(uint2*)(g_ah + rowoff + i * 4) =
                make_uint2(packh2(e.x * inv, e.y * inv), packh2(e.z * inv, e.w * inv));
        }
        __syncthreads();
    }
}

// ---------------------------------------------------------------------------
// Kernel C: out[b] = attn[b] @ values[b] via mma.sync fp16, single product.
// CTA tile M=32 x N=64, BK=64, 32 chunks. 8 warps = 2(m)x4(n); warp 16x16.
// Grid (8, 8, 4) = 256 CTAs, 13.8KB SMEM -> 2 CTAs/SM. (Measured-best R10.)
// ---------------------------------------------------------------------------
__global__ __launch_bounds__(256) void av_mma_kernel(float* __restrict__ out)
{
    __shared__ __align__(16) u16 sA[32 * 72];
    __shared__ __align__(16) u16 sB[64 * 72];

    const int tid = threadIdx.x;
    const int wid = tid >> 5;
    const int lane = tid & 31;

    const int b  = blockIdx.z;
    const int m0 = blockIdx.y * 32;
    const int n0 = blockIdx.x * 64;

    const int wm0 = (wid >> 2) * 16;   // 0,16
    const int wn0 = (wid & 3) * 16;    // 0,16,32,48

    const int lrow = tid >> 3;         // 0..31
    const int lg   = tid & 7;

    const uint4* gA = (const uint4*)(g_ah + (size_t)(b * QQ + m0) * VV);
    const uint4* gB = (const uint4*)(g_vth + (size_t)(b * HH + n0) * VV);
    const int RW = VV / 8;

    float dacc[2][4];
#pragma unroll
    for (int j = 0; j < 2; j++)
#pragma unroll
        for (int c = 0; c < 4; c++) dacc[j][c] = 0.f;

    uint4 pA, pB[2];
    pA = gA[(size_t)lrow * RW + lg];
#pragma unroll
    for (int i = 0; i < 2; i++)
        pB[i] = gB[(size_t)(lrow + i * 32) * RW + lg];

    const u32 bA = smem_u32(sA), bB = smem_u32(sB);

    const int arow = wm0 + (lane & 15);
    const u32 aoff = (u32)(arow * 9 + (lane >> 4)) * 16;
    const int brow = wn0 + (lane & 7);
    const u32 boff = (u32)(brow * 9 + ((lane >> 3) & 1)) * 16;

    const int NCH = VV / 64;   // 32

    for (int c = 0; c < NCH; c++) {
        {
            u32 s = (u32)(lrow * 9 + lg) * 8;
            *(uint4*)(sA + s) = pA;
        }
#pragma unroll
        for (int i = 0; i < 2; i++) {
            u32 s = (u32)((lrow + i * 32) * 9 + lg) * 8;
            *(uint4*)(sB + s) = pB[i];
        }
        if (c + 1 < NCH) {
            int g0 = (c + 1) * 8;
            pA = gA[(size_t)lrow * RW + g0 + lg];
#pragma unroll
            for (int i = 0; i < 2; i++)
                pB[i] = gB[(size_t)(lrow + i * 32) * RW + g0 + lg];
        }
        __syncthreads();

#pragma unroll
        for (int kb = 0; kb < 4; kb++) {
            u32 kadd = (u32)(kb * 2) * 16;
            u32 a[4], bb[2][2];
            ldsm4(a[0], a[1], a[2], a[3], bA + aoff + kadd);
#pragma unroll
            for (int nf = 0; nf < 2; nf++) {
                u32 bd = (u32)(nf * 8 * 9) * 16 + boff + kadd;
                ldsm2(bb[nf][0], bb[nf][1], bB + bd);
            }
#pragma unroll
            for (int nf = 0; nf < 2; nf++)
                mma_fp(dacc[nf], a, bb[nf]);
        }
        __syncthreads();
    }

    const int g = lane >> 2;
    const int t = lane & 3;
#pragma unroll
    for (int nf = 0; nf < 2; nf++) {
        int row = m0 + wm0 + g;
        int col = n0 + wn0 + nf * 8 + t * 2;
        float2 v0, v1;
        v0.x = dacc[nf][0]; v0.y = dacc[nf][1];
        v1.x = dacc[nf][2]; v1.y = dacc[nf][3];
        *(float2*)(out + (size_t)(b * QQ + row) * HH + col) = v0;
        *(float2*)(out + (size_t)(b * QQ + row + 8) * HH + col) = v1;
    }
}

// ---------------------------------------------------------------------------
extern "C" void kernel_launch(void* const* d_in, const int* in_sizes, int n_in,
                              void* d_out, int out_size)
{
    const float* queries = (const float*)d_in[0];
    const float* values  = (const float*)d_in[1];
    const float* w1      = (const float*)d_in[2];
    const float* w2      = (const float*)d_in[3];
    const float* vvec    = (const float*)d_in[4];
    float* out = (float*)d_out;

    const int smemB = (2592 + NQMAX * VV + 1792) * 4;  // 74,880 B
    cudaFuncSetAttribute(score_kernel,
                         cudaFuncAttributeMaxDynamicSharedMemorySize, smemB);

    wconv_kernel<<<32, 256>>>(w1, w2);
    proj_conv_kernel<<<144 + 1024, 256>>>(queries, values);
    score_kernel<<<SCORE_GRID, 256, smemB>>>(vvec);
    av_mma_kernel<<<dim3(HH / 64, QQ / 32, BB), 256>>>(out);
}

// round 13
// speedup vs baseline: 1.0816x; 1.0293x over previous
#include <cuda_runtime.h>
#include <cuda_fp16.h>

#define BB 4
#define QQ 256
#define VV 2048
#define HH 512
#define UU 128

typedef unsigned int       u32;
typedef unsigned long long u64;
typedef unsigned short     u16;

// Scratch (device globals: allocation-free rule)
__device__ float g_pq[BB * QQ * UU];          // [B,Q,U] fp32
__device__ float g_pv[BB * VV * UU];          // [B,V,U] fp32
__device__ u16   g_ah[BB * QQ * VV];          // attn fp16 [B,Q,V]
__device__ u16   g_vth[BB * HH * VV];         // values^T fp16 [B,H,V]
__device__ u16   g_w1th[UU * HH];             // w1^T fp16 [U,H]
__device__ u16   g_w2th[UU * HH];             // w2^T fp16 [U,H]

__device__ __forceinline__ u32 smem_u32(const void* p) {
    u32 a;
    asm("{ .reg .u64 t; cvta.to.shared.u64 t, %1; cvt.u32.u64 %0, t; }"
        : "=r"(a) : "l"(p));
    return a;
}
__device__ __forceinline__ void ldsm4(u32& r0, u32& r1, u32& r2, u32& r3, u32 a) {
    asm volatile("ldmatrix.sync.aligned.m8n8.x4.shared.b16 {%0,%1,%2,%3}, [%4];"
                 : "=r"(r0), "=r"(r1), "=r"(r2), "=r"(r3) : "r"(a));
}
__device__ __forceinline__ void ldsm2(u32& r0, u32& r1, u32 a) {
    asm volatile("ldmatrix.sync.aligned.m8n8.x2.shared.b16 {%0,%1}, [%2];"
                 : "=r"(r0), "=r"(r1) : "r"(a));
}
__device__ __forceinline__ void mma_fp(float* d, const u32* a, const u32* b) {
    asm volatile(
        "mma.sync.aligned.m16n8k16.row.col.f32.f16.f16.f32 "
        "{%0,%1,%2,%3}, {%4,%5,%6,%7}, {%8,%9}, {%0,%1,%2,%3};"
        : "+f"(d[0]), "+f"(d[1]), "+f"(d[2]), "+f"(d[3])
        : "r"(a[0]), "r"(a[1]), "r"(a[2]), "r"(a[3]), "r"(b[0]), "r"(b[1]));
}
__device__ __forceinline__ u32 packh2(float a, float b) {
    u32 r;
    asm("cvt.rn.f16x2.f32 %0, %2, %1;" : "=r"(r) : "f"(a), "f"(b));  // lo=a, hi=b
    return r;
}
__device__ __forceinline__ u32 hadd2(u32 a, u32 b) {
    u32 r; asm("add.rn.f16x2 %0, %1, %2;" : "=r"(r) : "r"(a), "r"(b)); return r;
}
__device__ __forceinline__ u32 hfma2(u32 a, u32 b, u32 c) {
    u32 r; asm("fma.rn.f16x2 %0, %1, %2, %3;" : "=r"(r) : "r"(a), "r"(b), "r"(c)); return r;
}
__device__ __forceinline__ u32 tanh2(u32 x) {
    u32 r; asm("tanh.approx.f16x2 %0, %1;" : "=r"(r) : "r"(x)); return r;
}
__device__ __forceinline__ float2 h2f2(u32 h) {
    __half2 hv = *reinterpret_cast<__half2*>(&h);
    return __half22float2(hv);
}
__device__ __forceinline__ void cp16(u32 dst, const void* src) {
    asm volatile("cp.async.cg.shared.global [%0], [%1], 16;" :: "r"(dst), "l"(src));
}
#define CP_COMMIT() asm volatile("cp.async.commit_group;" ::: "memory")
#define CP_WAIT(n)  asm volatile("cp.async.wait_group %0;" :: "n"(n) : "memory")

// ---------------------------------------------------------------------------
// Kernel 0: w1/w2 transpose -> fp16 (32 blocks; must precede proj).
// ---------------------------------------------------------------------------
__global__ __launch_bounds__(256) void wconv_kernel(
    const float* __restrict__ w1, const float* __restrict__ w2)
{
    __shared__ float ts[64 * 65];
    const int wb = blockIdx.x, tid = threadIdx.x;
    const float* W = (wb < 16) ? w1 : w2;
    u16* dh = (wb < 16) ? g_w1th : g_w2th;
    const int t = wb & 15;
    const int h0 = (t & 7) * 64, u0 = (t >> 3) * 64;
    const int r = tid >> 2, c0 = tid & 3;
#pragma unroll
    for (int it = 0; it < 4; it++) {
        int c4 = c0 * 4 + it;
        float4 f = ((const float4*)(W + (size_t)(h0 + r) * UU + u0))[c4];
        ts[r * 65 + c4 * 4 + 0] = f.x;
        ts[r * 65 + c4 * 4 + 1] = f.y;
        ts[r * 65 + c4 * 4 + 2] = f.z;
        ts[r * 65 + c4 * 4 + 3] = f.w;
    }
    __syncthreads();
    const int ur = tid >> 2, s0 = tid & 3;
#pragma unroll
    for (int it = 0; it < 4; it++) {
        int hs = s0 * 4 + it;
        float f0 = ts[(hs * 4 + 0) * 65 + ur];
        float f1 = ts[(hs * 4 + 1) * 65 + ur];
        float f2 = ts[(hs * 4 + 2) * 65 + ur];
        float f3 = ts[(hs * 4 + 3) * 65 + ur];
        size_t off = (size_t)(u0 + ur) * HH + h0 + hs * 4;
        *(uint2*)(dh + off) = make_uint2(packh2(f0, f1), packh2(f2, f3));
    }
}

// ---------------------------------------------------------------------------
// Kernel A (FUSED): blocks [0,144) = projections (mma.sync fp16, single
// product); blocks [144,1200) = values 64x64 tiles -> g_vth (transposed fp16).
// proj: CTA tile M=64 x N=128(=U), BK=64, 8 chunks. 8 warps = 2(m)x4(n).
// ---------------------------------------------------------------------------
__global__ __launch_bounds__(256) void proj_conv_kernel(
    const float* __restrict__ queries, const float* __restrict__ values)
{
    __shared__ __align__(16) char sm[27648];
    const int tid = threadIdx.x;
    const int bx = blockIdx.x;

    if (bx >= 144) {
        // ---- values^T conversion branch ----
        float* ts = (float*)sm;               // 64*65 floats
        const int vb = bx - 144;
        const int b = vb >> 8, t = vb & 255;
        const int v0 = (t & 31) * 64, h0 = (t >> 5) * 64;
        const int r = tid >> 2, c0 = tid & 3;
#pragma unroll
        for (int it = 0; it < 4; it++) {
            int c4 = c0 * 4 + it;
            float4 f = ((const float4*)(values + (size_t)(b * VV + v0 + r) * HH + h0))[c4];
            ts[r * 65 + c4 * 4 + 0] = f.x;
            ts[r * 65 + c4 * 4 + 1] = f.y;
            ts[r * 65 + c4 * 4 + 2] = f.z;
            ts[r * 65 + c4 * 4 + 3] = f.w;
        }
        __syncthreads();
        const int hr = tid >> 2, s0 = tid & 3;
#pragma unroll
        for (int it = 0; it < 4; it++) {
            int vs = s0 * 4 + it;
            float f0 = ts[(vs * 4 + 0) * 65 + hr];
            float f1 = ts[(vs * 4 + 1) * 65 + hr];
            float f2 = ts[(vs * 4 + 2) * 65 + hr];
            float f3 = ts[(vs * 4 + 3) * 65 + hr];
            size_t off = (size_t)(b * HH + h0 + hr) * VV + v0 + vs * 4;
            *(uint2*)(g_vth + off) = make_uint2(packh2(f0, f1), packh2(f2, f3));
        }
        return;
    }

    // ---- projection branch ----
    u16* sA = (u16*)sm;                 //  64*72 u16
    u16* sB = (u16*)(sm + 9216);        // 128*72 u16

    const int wid = tid >> 5;
    const int lane = tid & 31;

    const float* Afp; const u16* Bw; float* C; int m0;
    if (bx < 128) { Afp = values;  Bw = g_w2th; C = g_pv; m0 = bx * 64; }
    else          { Afp = queries; Bw = g_w1th; C = g_pq; m0 = (bx - 128) * 64; }

    const int wm0 = (wid >> 2) * 32;
    const int wn0 = (wid & 3) * 32;

    const int ar = tid >> 2, ac4 = tid & 3;
    const int br = tid >> 1, bg = tid & 1;

    const float4* gA4 = (const float4*)(Afp + (size_t)m0 * HH);
    const uint4* gB4 = (const uint4*)Bw;
    const int RWA = HH / 4;
    const int RWB = HH / 8;

    float dacc[2][4][4];
#pragma unroll
    for (int i = 0; i < 2; i++)
#pragma unroll
        for (int j = 0; j < 4; j++)
#pragma unroll
            for (int c = 0; c < 4; c++) dacc[i][j][c] = 0.f;

    float4 pA[4];
    uint4 pB[4];
#pragma unroll
    for (int it = 0; it < 4; it++)
        pA[it] = gA4[(size_t)ar * RWA + ac4 * 4 + it];
#pragma unroll
    for (int j = 0; j < 4; j++)
        pB[j] = gB4[(size_t)br * RWB + bg * 4 + j];

    const u32 bA = smem_u32(sA), bB = smem_u32(sB);

    const int arow = wm0 + (lane & 15);
    const u32 aoff = (u32)(arow * 9 + (lane >> 4)) * 16;
    const int brow_base = ((lane >> 4) << 3) + (lane & 7);
    const int bgr = (lane >> 3) & 1;

    const int NCH = HH / 64;   // 8

    for (int c = 0; c < NCH; c++) {
#pragma unroll
        for (int it = 0; it < 4; it++) {
            u32 h01 = packh2(pA[it].x, pA[it].y);
            u32 h23 = packh2(pA[it].z, pA[it].w);
            u32 s = (u32)(ar * 72 + (ac4 * 4 + it) * 4);
            *(uint2*)(sA + s) = make_uint2(h01, h23);
        }
#pragma unroll
        for (int j = 0; j < 4; j++) {
            u32 s = (u32)(br * 72 + (bg * 4 + j) * 8);
            *(uint4*)(sB + s) = pB[j];
        }
        if (c + 1 < NCH) {
            int fa = (c + 1) * 16, fb = (c + 1) * 8;
#pragma unroll
            for (int it = 0; it < 4; it++)
                pA[it] = gA4[(size_t)ar * RWA + fa + ac4 * 4 + it];
#pragma unroll
            for (int j = 0; j < 4; j++)
                pB[j] = gB4[(size_t)br * RWB + fb + bg * 4 + j];
        }
        __syncthreads();

#pragma unroll
        for (int kb = 0; kb < 4; kb++) {
            u32 a[2][4], bb[4][2];
#pragma unroll
            for (int mf = 0; mf < 2; mf++) {
                u32 ad = (u32)((mf * 16) * 9) * 16 + aoff + (u32)(kb * 2) * 16;
                ldsm4(a[mf][0], a[mf][1], a[mf][2], a[mf][3], bA + ad);
            }
#pragma unroll
            for (int p = 0; p < 2; p++) {
                int row = wn0 + p * 16 + brow_base;
                u32 bd = (u32)(row * 9 + kb * 2 + bgr) * 16;
                u32 r0, r1, r2, r3;
                ldsm4(r0, r1, r2, r3, bB + bd);
                bb[p * 2 + 0][0] = r0; bb[p * 2 + 0][1] = r1;
                bb[p * 2 + 1][0] = r2; bb[p * 2 + 1][1] = r3;
            }
#pragma unroll
            for (int mf = 0; mf < 2; mf++)
#pragma unroll
                for (int nf = 0; nf < 4; nf++)
                    mma_fp(dacc[mf][nf], a[mf], bb[nf]);
        }
        __syncthreads();
    }

    const int g = lane >> 2;
    const int t = lane & 3;
#pragma unroll
    for (int mf = 0; mf < 2; mf++)
#pragma unroll
        for (int nf = 0; nf < 4; nf++) {
            int row = m0 + wm0 + mf * 16 + g;
            int col = wn0 + nf * 8 + t * 2;
            float2 v0, v1;
            v0.x = dacc[mf][nf][0]; v0.y = dacc[mf][nf][1];
            v1.x = dacc[mf][nf][2]; v1.y = dacc[mf][nf][3];
            *(float2*)(C + (size_t)row * UU + col) = v0;
            *(float2*)(C + (size_t)(row + 8) * UU + col) = v1;
        }
}

// ---------------------------------------------------------------------------
// Kernel B: scores + softmax -> attn (fp16). Persistent 148 CTAs.
// Packed f16x2 pipeline (proven R12). Dynamic SMEM = 74,880 B.
// ---------------------------------------------------------------------------
#define SCORE_GRID 148
#define CPB 37
#define NQMAX 7

__global__ __launch_bounds__(256) void score_kernel(const float* __restrict__ vvec)
{
    extern __shared__ u32 smu[];
    u32*   pvs2 = smu;                         // 32*65 = 2080 u32
    u32*   pqs2 = smu + 2080;                  // 448 u32
    u32*   vs2  = smu + 2528;                  // 64 u32
    float* scores = (float*)(smu + 2592);      // 7*2048 floats
    float* sp     = scores + NQMAX * VV;       // 1792 floats

    const int tid = threadIdx.x;
    const int b     = blockIdx.x / CPB;
    const int local = blockIdx.x % CPB;
    const int nq = (local < 34) ? 7 : 6;
    const int q0 = (local < 34) ? local * 7 : 238 + (local - 34) * 6;

    if (tid < nq * 32) {
        int q = tid >> 5, j = tid & 31;
        float4 f = ((const float4*)(g_pq + (size_t)(b * QQ + q0 + q) * UU))[j];
        pqs2[q * 64 + 2 * j]     = packh2(f.x, f.y);
        pqs2[q * 64 + 2 * j + 1] = packh2(f.z, f.w);
    }
    if (tid < 32) {
        float4 wv = ((const float4*)vvec)[tid];
        vs2[2 * tid]     = packh2(wv.x, wv.y);
        vs2[2 * tid + 1] = packh2(wv.z, wv.w);
    }

    const float4* pv4 = (const float4*)g_pv;
    const int r  = tid & 31;
    const int ug = tid >> 5;
    const int lrr = tid >> 5;
    const int lc  = tid & 31;

    float4 pf[4];
#pragma unroll
    for (int i = 0; i < 4; i++)
        pf[i] = pv4[(size_t)(b * VV + lrr + i * 8) * 32 + lc];

    __syncthreads();

    u32 vw2[8];
#pragma unroll
    for (int u2 = 0; u2 < 8; u2++) vw2[u2] = vs2[ug * 8 + u2];

    for (int vt = 0; vt < VV; vt += 32) {
#pragma unroll
        for (int i = 0; i < 4; i++) {
            int row = lrr + i * 8;
            pvs2[row * 65 + 2 * lc]     = packh2(pf[i].x, pf[i].y);
            pvs2[row * 65 + 2 * lc + 1] = packh2(pf[i].z, pf[i].w);
        }
        if (vt + 32 < VV) {
#pragma unroll
            for (int i = 0; i < 4; i++)
                pf[i] = pv4[(size_t)(b * VV + vt + 32 + lrr + i * 8) * 32 + lc];
        }
        __syncthreads();

        u32 acc2[NQMAX];
#pragma unroll
        for (int q = 0; q < NQMAX; q++) acc2[q] = 0u;

        const u32* prow = pvs2 + r * 65 + ug * 8;
#pragma unroll
        for (int u2 = 0; u2 < 8; u2++) {
            u32 p2 = prow[u2];
            u32 w2 = vw2[u2];
#pragma unroll
            for (int q = 0; q < NQMAX; q++) {
                u32 q2 = pqs2[q * 64 + ug * 8 + u2];
                acc2[q] = hfma2(tanh2(hadd2(q2, p2)), w2, acc2[q]);
            }
        }
#pragma unroll
        for (int q = 0; q < NQMAX; q++) {
            float2 t = h2f2(acc2[q]);
            sp[q * 256 + tid] = t.x + t.y;
        }
        __syncthreads();

        if (tid < 224) {
            int q = tid >> 5, rr = tid & 31;
            float s = 0.f;
#pragma unroll
            for (int u = 0; u < 8; u++) s += sp[q * 256 + u * 32 + rr];
            scores[q * VV + vt + rr] = s;
        }
        __syncthreads();
    }

    float* red = sp;
    for (int qi = 0; qi < nq; qi++) {
        float* sc = scores + qi * VV;

        float m = -1e30f;
        for (int i = tid; i < VV; i += 256) m = fmaxf(m, sc[i]);
        red[tid] = m;
        __syncthreads();
        for (int s = 128; s > 0; s >>= 1) {
            if (tid < s) red[tid] = fmaxf(red[tid], red[tid + s]);
            __syncthreads();
        }
        m = red[0];
        __syncthreads();

        float lsum = 0.f;
        for (int i = tid; i < VV; i += 256) {
            float e = __expf(sc[i] - m);
            sc[i] = e;
            lsum += e;
        }
        red[tid] = lsum;
        __syncthreads();
        for (int s = 128; s > 0; s >>= 1) {
            if (tid < s) red[tid] += red[tid + s];
            __syncthreads();
        }
        float inv = 1.f / red[0];
        __syncthreads();

        size_t rowoff = (size_t)(b * QQ + q0 + qi) * VV;
        const float4* sc4 = (const float4*)sc;
        for (int i = tid; i < VV / 4; i += 256) {
            float4 e = sc4[i];
            *(uint2*)(g_ah + rowoff + i * 4) =
                make_uint2(packh2(e.x * inv, e.y * inv), packh2(e.z * inv, e.w * inv));
        }
        __syncthreads();
    }
}

// ---------------------------------------------------------------------------
// Kernel C: out[b] = attn[b] @ values[b] via mma.sync fp16, single product,
// 4-STAGE cp.async PIPELINE. CTA tile M=32 x N=64, BK=64, 32 chunks.
// 8 warps = 2(m)x4(n); warp 16x16. Grid (8,8,4) = 256 CTAs.
// SMEM = 4 x (32+64) x 72 x 2B = 55,296 B static -> 2 CTAs/SM.
// Per iter: wait(2) -> sync -> issue chunk c+3 -> compute chunk c.
// ---------------------------------------------------------------------------
#define AVS 4

__global__ __launch_bounds__(256) void av_mma_kernel(float* __restrict__ out)
{
    __shared__ __align__(16) u16 sA[AVS][32 * 72];
    __shared__ __align__(16) u16 sB[AVS][64 * 72];

    const int tid = threadIdx.x;
    const int wid = tid >> 5;
    const int lane = tid & 31;

    const int b  = blockIdx.z;
    const int m0 = blockIdx.y * 32;
    const int n0 = blockIdx.x * 64;

    const int wm0 = (wid >> 2) * 16;   // 0,16
    const int wn0 = (wid & 3) * 16;    // 0,16,32,48

    const int lrow = tid >> 3;         // 0..31
    const int lg   = tid & 7;

    const uint4* gA = (const uint4*)(g_ah + (size_t)(b * QQ + m0) * VV);
    const uint4* gB = (const uint4*)(g_vth + (size_t)(b * HH + n0) * VV);
    const int RW = VV / 8;

    // per-thread SMEM dst offsets (bytes)
    const u32 aDst = (u32)(lrow * 9 + lg) * 16;
    const u32 bDst0 = aDst;
    const u32 bDst1 = (u32)((lrow + 32) * 9 + lg) * 16;

    u32 aStg[AVS], bStg[AVS];
#pragma unroll
    for (int s = 0; s < AVS; s++) {
        aStg[s] = smem_u32(sA[s]);
        bStg[s] = smem_u32(sB[s]);
    }

    float dacc[2][4];
#pragma unroll
    for (int j = 0; j < 2; j++)
#pragma unroll
        for (int c = 0; c < 4; c++) dacc[j][c] = 0.f;

    const int NCH = VV / 64;   // 32

    // prologue: stages 0..AVS-2 in flight
#pragma unroll
    for (int s = 0; s < AVS - 1; s++) {
        cp16(aStg[s] + aDst, gA + (size_t)lrow * RW + s * 8 + lg);
        cp16(bStg[s] + bDst0, gB + (size_t)lrow * RW + s * 8 + lg);
        cp16(bStg[s] + bDst1, gB + (size_t)(lrow + 32) * RW + s * 8 + lg);
        CP_COMMIT();
    }

    const int arow = wm0 + (lane & 15);
    const u32 aoff = (u32)(arow * 9 + (lane >> 4)) * 16;
    const int brow = wn0 + (lane & 7);
    const u32 boff = (u32)(brow * 9 + ((lane >> 3) & 1)) * 16;

    for (int c = 0; c < NCH; c++) {
        CP_WAIT(AVS - 2);          // chunk c resident
        __syncthreads();

        // issue chunk c+AVS-1 into stage (c-1)%AVS (safe: computed last iter)
        int cn = c + AVS - 1;
        if (cn < NCH) {
            int s = cn & (AVS - 1);
            cp16(aStg[s] + aDst, gA + (size_t)lrow * RW + cn * 8 + lg);
            cp16(bStg[s] + bDst0, gB + (size_t)lrow * RW + cn * 8 + lg);
            cp16(bStg[s] + bDst1, gB + (size_t)(lrow + 32) * RW + cn * 8 + lg);
        }
        CP_COMMIT();               // always commit to keep group count aligned

        const u32 bA = aStg[c & (AVS - 1)];
        const u32 bBs = bStg[c & (AVS - 1)];
#pragma unroll
        for (int kb = 0; kb < 4; kb++) {
            u32 kadd = (u32)(kb * 2) * 16;
            u32 a[4], bb[2][2];
            ldsm4(a[0], a[1], a[2], a[3], bA + aoff + kadd);
#pragma unroll
            for (int nf = 0; nf < 2; nf++) {
                u32 bd = (u32)(nf * 8 * 9) * 16 + boff + kadd;
                ldsm2(bb[nf][0], bb[nf][1], bBs + bd);
            }
#pragma unroll
            for (int nf = 0; nf < 2; nf++)
                mma_fp(dacc[nf], a, bb[nf]);
        }
    }

    const int g = lane >> 2;
    const int t = lane & 3;
#pragma unroll
    for (int nf = 0; nf < 2; nf++) {
        int row = m0 + wm0 + g;
        int col = n0 + wn0 + nf * 8 + t * 2;
        float2 v0, v1;
        v0.x = dacc[nf][0]; v0.y = dacc[nf][1];
        v1.x = dacc[nf][2]; v1.y = dacc[nf][3];
        *(float2*)(out + (size_t)(b * QQ + row) * HH + col) = v0;
        *(float2*)(out + (size_t)(b * QQ + row + 8) * HH + col) = v1;
    }
}

// ---------------------------------------------------------------------------
extern "C" void kernel_launch(void* const* d_in, const int* in_sizes, int n_in,
                              void* d_out, int out_size)
{
    const float* queries = (const float*)d_in[0];
    const float* values  = (const float*)d_in[1];
    const float* w1      = (const float*)d_in[2];
    const float* w2      = (const float*)d_in[3];
    const float* vvec    = (const float*)d_in[4];
    float* out = (float*)d_out;

    const int smemB = (2592 + NQMAX * VV + 1792) * 4;  // 74,880 B
    cudaFuncSetAttribute(score_kernel,
                         cudaFuncAttributeMaxDynamicSharedMemorySize, smemB);

    wconv_kernel<<<32, 256>>>(w1, w2);
    proj_conv_kernel<<<144 + 1024, 256>>>(queries, values);
    score_kernel<<<SCORE_GRID, 256, smemB>>>(vvec);
    av_mma_kernel<<<dim3(HH / 64, QQ / 32, BB), 256>>>(out);
}

// round 14
// speedup vs baseline: 1.1435x; 1.0572x over previous
#include <cuda_runtime.h>
#include <cuda_fp16.h>

#define BB 4
#define QQ 256
#define VV 2048
#define HH 512
#define UU 128

typedef unsigned int       u32;
typedef unsigned long long u64;
typedef unsigned short     u16;

// Scratch (device globals: allocation-free rule)
__device__ float g_pq[BB * QQ * UU];          // [B,Q,U] fp32
__device__ float g_pv[BB * VV * UU];          // [B,V,U] fp32
__device__ u16   g_ah[BB * QQ * VV];          // attn fp16 [B,Q,V]
__device__ u16   g_vh[BB * VV * HH];          // values fp16 [B,V,H] row-major
__device__ u16   g_qh[BB * QQ * HH];          // queries fp16 [B,Q,H]
__device__ u16   g_w1h[HH * UU];              // w1 fp16 [H,U] row-major
__device__ u16   g_w2h[HH * UU];              // w2 fp16 [H,U]

__device__ __forceinline__ u32 smem_u32(const void* p) {
    u32 a;
    asm("{ .reg .u64 t; cvta.to.shared.u64 t, %1; cvt.u32.u64 %0, t; }"
        : "=r"(a) : "l"(p));
    return a;
}
__device__ __forceinline__ void ldsm4(u32& r0, u32& r1, u32& r2, u32& r3, u32 a) {
    asm volatile("ldmatrix.sync.aligned.m8n8.x4.shared.b16 {%0,%1,%2,%3}, [%4];"
                 : "=r"(r0), "=r"(r1), "=r"(r2), "=r"(r3) : "r"(a));
}
__device__ __forceinline__ void ldsm4t(u32& r0, u32& r1, u32& r2, u32& r3, u32 a) {
    asm volatile("ldmatrix.sync.aligned.m8n8.x4.trans.shared.b16 {%0,%1,%2,%3}, [%4];"
                 : "=r"(r0), "=r"(r1), "=r"(r2), "=r"(r3) : "r"(a));
}
__device__ __forceinline__ void mma_fp(float* d, const u32* a, const u32* b) {
    asm volatile(
        "mma.sync.aligned.m16n8k16.row.col.f32.f16.f16.f32 "
        "{%0,%1,%2,%3}, {%4,%5,%6,%7}, {%8,%9}, {%0,%1,%2,%3};"
        : "+f"(d[0]), "+f"(d[1]), "+f"(d[2]), "+f"(d[3])
        : "r"(a[0]), "r"(a[1]), "r"(a[2]), "r"(a[3]), "r"(b[0]), "r"(b[1]));
}
__device__ __forceinline__ u32 packh2(float a, float b) {
    u32 r;
    asm("cvt.rn.f16x2.f32 %0, %2, %1;" : "=r"(r) : "f"(a), "f"(b));  // lo=a, hi=b
    return r;
}
__device__ __forceinline__ u32 hadd2(u32 a, u32 b) {
    u32 r; asm("add.rn.f16x2 %0, %1, %2;" : "=r"(r) : "r"(a), "r"(b)); return r;
}
__device__ __forceinline__ u32 hfma2(u32 a, u32 b, u32 c) {
    u32 r; asm("fma.rn.f16x2 %0, %1, %2, %3;" : "=r"(r) : "r"(a), "r"(b), "r"(c)); return r;
}
__device__ __forceinline__ u32 tanh2(u32 x) {
    u32 r; asm("tanh.approx.f16x2 %0, %1;" : "=r"(r) : "r"(x)); return r;
}
__device__ __forceinline__ float2 h2f2(u32 h) {
    __half2 hv = *reinterpret_cast<__half2*>(&h);
    return __half22float2(hv);
}
__device__ __forceinline__ void cp16(u32 dst, const void* src) {
    asm volatile("cp.async.cg.shared.global [%0], [%1], 16;" :: "r"(dst), "l"(src));
}
#define CP_COMMIT() asm volatile("cp.async.commit_group;" ::: "memory")
#define CP_WAIT(n)  asm volatile("cp.async.wait_group %0;" :: "n"(n) : "memory")

// ---------------------------------------------------------------------------
// Kernel 0: elementwise fp32 -> fp16 of values, queries, w1, w2.
//   blocks [0,1024):    values   (1,048,576 float4)
//   blocks [1024,1152): queries  (131,072 float4)
//   blocks [1152,1168): w1       (16,384 float4)
//   blocks [1168,1184): w2       (16,384 float4)
// Each block: 1024 float4 (4 per thread). No SMEM, no syncs.
// ---------------------------------------------------------------------------
__global__ __launch_bounds__(256) void conv_kernel(
    const float* __restrict__ queries, const float* __restrict__ values,
    const float* __restrict__ w1, const float* __restrict__ w2)
{
    const int bx = blockIdx.x, tid = threadIdx.x;
    const float4* src; u16* dst; size_t base;
    if (bx < 1024)      { src = (const float4*)values;  dst = g_vh;  base = (size_t)bx * 1024; }
    else if (bx < 1152) { src = (const float4*)queries; dst = g_qh;  base = (size_t)(bx - 1024) * 1024; }
    else if (bx < 1168) { src = (const float4*)w1;      dst = g_w1h; base = (size_t)(bx - 1152) * 1024; }
    else                { src = (const float4*)w2;      dst = g_w2h; base = (size_t)(bx - 1168) * 1024; }

#pragma unroll
    for (int i = 0; i < 4; i++) {
        size_t idx = base + i * 256 + tid;
        float4 f = src[idx];
        *(uint2*)(dst + idx * 4) = make_uint2(packh2(f.x, f.y), packh2(f.z, f.w));
    }
}

// ---------------------------------------------------------------------------
// Kernel A: projections, all-fp16 mma.sync, register relay.
//   blocks [0,128):  pv = values_h @ w2_h;  blocks [128,144): pq = queries_h @ w1_h
// A row-major [M,K=H] fp16 (ldsm4); B row-major [K=H, N=U] fp16 (ldsm4.trans).
// CTA tile M=64 x N=128, BK=64, 8 chunks. 8 warps = 2(m)x4(n), warp 32x32.
// SMEM: sA 64x72 u16 (9216B) + sB 64x136 u16 (17408B).
// ---------------------------------------------------------------------------
__global__ __launch_bounds__(256) void proj_tc_kernel()
{
    __shared__ __align__(16) u16 sA[64 * 72];
    __shared__ __align__(16) u16 sB[64 * 136];

    const int tid = threadIdx.x;
    const int wid = tid >> 5;
    const int lane = tid & 31;
    const int bx = blockIdx.x;

    const u16* Ah; const u16* Bw; float* C; int m0;
    if (bx < 128) { Ah = g_vh; Bw = g_w2h; C = g_pv; m0 = bx * 64; }
    else          { Ah = g_qh; Bw = g_w1h; C = g_pq; m0 = (bx - 128) * 64; }

    const int wm0 = (wid >> 2) * 32;   // 0,32
    const int wn0 = (wid & 3) * 32;    // 0,32,64,96

    // global load coords
    const int ar = tid >> 2, ag = (tid & 3) * 2;   // A: 64 rows x 8 granules (2/thr)
    const int br = tid >> 2, bg = (tid & 3) * 4;   // B: 64 rows x 16 granules (4/thr)

    const uint4* gA = (const uint4*)(Ah + (size_t)m0 * HH);
    const uint4* gB = (const uint4*)Bw;
    const int RWA = HH / 8;   // 64 granules per A row
    const int RWB = UU / 8;   // 16 granules per B row

    float dacc[2][4][4];
#pragma unroll
    for (int i = 0; i < 2; i++)
#pragma unroll
        for (int j = 0; j < 4; j++)
#pragma unroll
            for (int c = 0; c < 4; c++) dacc[i][j][c] = 0.f;

    uint4 pA[2], pB[4];
#pragma unroll
    for (int j = 0; j < 2; j++)
        pA[j] = gA[(size_t)ar * RWA + ag + j];
#pragma unroll
    for (int j = 0; j < 4; j++)
        pB[j] = gB[(size_t)br * RWB + bg + j];

    const u32 bA = smem_u32(sA), bB = smem_u32(sB);

    // ldmatrix addressing
    const int arow = wm0 + (lane & 15);
    const u32 aoff = (u32)(arow * 9 + (lane >> 4)) * 16;
    // trans-B: row (k=h) lane part, col (n=u) granule
    const int trow = (lane & 7) + ((lane >> 3) & 1) * 8;
    const int tcolg = lane >> 4;                   // 0 or 1 (8-u granule)

    const int NCH = HH / 64;   // 8

    for (int c = 0; c < NCH; c++) {
        // store chunk c
#pragma unroll
        for (int j = 0; j < 2; j++) {
            u32 s = (u32)(ar * 9 + ag + j) * 8;
            *(uint4*)(sA + s) = pA[j];
        }
#pragma unroll
        for (int j = 0; j < 4; j++) {
            u32 s = (u32)(br * 17 + bg + j) * 8;
            *(uint4*)(sB + s) = pB[j];
        }
        // prefetch chunk c+1
        if (c + 1 < NCH) {
            int fa = (c + 1) * 8, fb = (c + 1) * 64;
#pragma unroll
            for (int j = 0; j < 2; j++)
                pA[j] = gA[(size_t)ar * RWA + fa + ag + j];
#pragma unroll
            for (int j = 0; j < 4; j++)
                pB[j] = gB[(size_t)(fb + br) * RWB + bg + j];
        }
        __syncthreads();

#pragma unroll
        for (int kb = 0; kb < 4; kb++) {
            u32 a[2][4], bb[4][2];
#pragma unroll
            for (int mf = 0; mf < 2; mf++) {
                u32 ad = (u32)(mf * 16 * 9) * 16 + aoff + (u32)(kb * 2) * 16;
                ldsm4(a[mf][0], a[mf][1], a[mf][2], a[mf][3], bA + ad);
            }
#pragma unroll
            for (int p = 0; p < 2; p++) {
                u32 bd = (u32)((kb * 16 + trow) * 17 + ((wn0 + p * 16) >> 3) + tcolg) * 16;
                u32 r0, r1, r2, r3;
                ldsm4t(r0, r1, r2, r3, bB + bd);
                bb[p * 2 + 0][0] = r0; bb[p * 2 + 0][1] = r1;
                bb[p * 2 + 1][0] = r2; bb[p * 2 + 1][1] = r3;
            }
#pragma unroll
            for (int mf = 0; mf < 2; mf++)
#pragma unroll
                for (int nf = 0; nf < 4; nf++)
                    mma_fp(dacc[mf][nf], a[mf], bb[nf]);
        }
        __syncthreads();
    }

    const int g = lane >> 2;
    const int t = lane & 3;
#pragma unroll
    for (int mf = 0; mf < 2; mf++)
#pragma unroll
        for (int nf = 0; nf < 4; nf++) {
            int row = m0 + wm0 + mf * 16 + g;
            int col = wn0 + nf * 8 + t * 2;
            float2 v0, v1;
            v0.x = dacc[mf][nf][0]; v0.y = dacc[mf][nf][1];
            v1.x = dacc[mf][nf][2]; v1.y = dacc[mf][nf][3];
            *(float2*)(C + (size_t)row * UU + col) = v0;
            *(float2*)(C + (size_t)(row + 8) * UU + col) = v1;
        }
}

// ---------------------------------------------------------------------------
// Kernel B: scores + softmax -> attn (fp16). Persistent 148 CTAs.
// Packed f16x2 pipeline (proven R12). Dynamic SMEM = 74,880 B.
// ---------------------------------------------------------------------------
#define SCORE_GRID 148
#define CPB 37
#define NQMAX 7

__global__ __launch_bounds__(256) void score_kernel(const float* __restrict__ vvec)
{
    extern __shared__ u32 smu[];
    u32*   pvs2 = smu;                         // 32*65 = 2080 u32
    u32*   pqs2 = smu + 2080;                  // 448 u32
    u32*   vs2  = smu + 2528;                  // 64 u32
    float* scores = (float*)(smu + 2592);      // 7*2048 floats
    float* sp     = scores + NQMAX * VV;       // 1792 floats

    const int tid = threadIdx.x;
    const int b     = blockIdx.x / CPB;
    const int local = blockIdx.x % CPB;
    const int nq = (local < 34) ? 7 : 6;
    const int q0 = (local < 34) ? local * 7 : 238 + (local - 34) * 6;

    if (tid < nq * 32) {
        int q = tid >> 5, j = tid & 31;
        float4 f = ((const float4*)(g_pq + (size_t)(b * QQ + q0 + q) * UU))[j];
        pqs2[q * 64 + 2 * j]     = packh2(f.x, f.y);
        pqs2[q * 64 + 2 * j + 1] = packh2(f.z, f.w);
    }
    if (tid < 32) {
        float4 wv = ((const float4*)vvec)[tid];
        vs2[2 * tid]     = packh2(wv.x, wv.y);
        vs2[2 * tid + 1] = packh2(wv.z, wv.w);
    }

    const float4* pv4 = (const float4*)g_pv;
    const int r  = tid & 31;
    const int ug = tid >> 5;
    const int lrr = tid >> 5;
    const int lc  = tid & 31;

    float4 pf[4];
#pragma unroll
    for (int i = 0; i < 4; i++)
        pf[i] = pv4[(size_t)(b * VV + lrr + i * 8) * 32 + lc];

    __syncthreads();

    u32 vw2[8];
#pragma unroll
    for (int u2 = 0; u2 < 8; u2++) vw2[u2] = vs2[ug * 8 + u2];

    for (int vt = 0; vt < VV; vt += 32) {
#pragma unroll
        for (int i = 0; i < 4; i++) {
            int row = lrr + i * 8;
            pvs2[row * 65 + 2 * lc]     = packh2(pf[i].x, pf[i].y);
            pvs2[row * 65 + 2 * lc + 1] = packh2(pf[i].z, pf[i].w);
        }
        if (vt + 32 < VV) {
#pragma unroll
            for (int i = 0; i < 4; i++)
                pf[i] = pv4[(size_t)(b * VV + vt + 32 + lrr + i * 8) * 32 + lc];
        }
        __syncthreads();

        u32 acc2[NQMAX];
#pragma unroll
        for (int q = 0; q < NQMAX; q++) acc2[q] = 0u;

        const u32* prow = pvs2 + r * 65 + ug * 8;
#pragma unroll
        for (int u2 = 0; u2 < 8; u2++) {
            u32 p2 = prow[u2];
            u32 w2 = vw2[u2];
#pragma unroll
            for (int q = 0; q < NQMAX; q++) {
                u32 q2 = pqs2[q * 64 + ug * 8 + u2];
                acc2[q] = hfma2(tanh2(hadd2(q2, p2)), w2, acc2[q]);
            }
        }
#pragma unroll
        for (int q = 0; q < NQMAX; q++) {
            float2 t = h2f2(acc2[q]);
            sp[q * 256 + tid] = t.x + t.y;
        }
        __syncthreads();

        if (tid < 224) {
            int q = tid >> 5, rr = tid & 31;
            float s = 0.f;
#pragma unroll
            for (int u = 0; u < 8; u++) s += sp[q * 256 + u * 32 + rr];
            scores[q * VV + vt + rr] = s;
        }
        __syncthreads();
    }

    float* red = sp;
    for (int qi = 0; qi < nq; qi++) {
        float* sc = scores + qi * VV;

        float m = -1e30f;
        for (int i = tid; i < VV; i += 256) m = fmaxf(m, sc[i]);
        red[tid] = m;
        __syncthreads();
        for (int s = 128; s > 0; s >>= 1) {
            if (tid < s) red[tid] = fmaxf(red[tid], red[tid + s]);
            __syncthreads();
        }
        m = red[0];
        __syncthreads();

        float lsum = 0.f;
        for (int i = tid; i < VV; i += 256) {
            float e = __expf(sc[i] - m);
            sc[i] = e;
            lsum += e;
        }
        red[tid] = lsum;
        __syncthreads();
        for (int s = 128; s > 0; s >>= 1) {
            if (tid < s) red[tid] += red[tid + s];
            __syncthreads();
        }
        float inv = 1.f / red[0];
        __syncthreads();

        size_t rowoff = (size_t)(b * QQ + q0 + qi) * VV;
        const float4* sc4 = (const float4*)sc;
        for (int i = tid; i < VV / 4; i += 256) {
            float4 e = sc4[i];
            *(uint2*)(g_ah + rowoff + i * 4) =
                make_uint2(packh2(e.x * inv, e.y * inv), packh2(e.z * inv, e.w * inv));
        }
        __syncthreads();
    }
}

// ---------------------------------------------------------------------------
// Kernel C: out[b] = attn[b] @ values[b], mma.sync fp16, 4-stage cp.async.
// B = values fp16 row-major [V,H] via ldsm4.trans (no pre-transpose).
// CTA tile M=32 x N=64, BK=64, 32 chunks. 8 warps = 2(m)x4(n); warp 16x16.
// Grid (8,8,4) = 256 CTAs. SMEM 55,296 B static.
// ---------------------------------------------------------------------------
#define AVS 4

__global__ __launch_bounds__(256) void av_mma_kernel(float* __restrict__ out)
{
    __shared__ __align__(16) u16 sA[AVS][32 * 72];
    __shared__ __align__(16) u16 sB[AVS][64 * 72];

    const int tid = threadIdx.x;
    const int wid = tid >> 5;
    const int lane = tid & 31;

    const int b  = blockIdx.z;
    const int m0 = blockIdx.y * 32;
    const int n0 = blockIdx.x * 64;

    const int wm0 = (wid >> 2) * 16;   // 0,16
    const int wn0 = (wid & 3) * 16;    // 0,16,32,48

    const int lrow = tid >> 3;         // 0..31
    const int lg   = tid & 7;

    const uint4* gA = (const uint4*)(g_ah + (size_t)(b * QQ + m0) * VV);
    const uint4* gB = (const uint4*)(g_vh + (size_t)b * VV * HH + n0);
    const int RWA = VV / 8;            // 256 granules per attn row
    const int RWB = HH / 8;            // 64 granules per values row

    const u32 aDst  = (u32)(lrow * 9 + lg) * 16;
    const u32 bDst0 = aDst;
    const u32 bDst1 = (u32)((lrow + 32) * 9 + lg) * 16;

    u32 aStg[AVS], bStg[AVS];
#pragma unroll
    for (int s = 0; s < AVS; s++) {
        aStg[s] = smem_u32(sA[s]);
        bStg[s] = smem_u32(sB[s]);
    }

    float dacc[2][4];
#pragma unroll
    for (int j = 0; j < 2; j++)
#pragma unroll
        for (int c = 0; c < 4; c++) dacc[j][c] = 0.f;

    const int NCH = VV / 64;   // 32

    // prologue: stages 0..AVS-2 in flight
#pragma unroll
    for (int s = 0; s < AVS - 1; s++) {
        cp16(aStg[s] + aDst, gA + (size_t)lrow * RWA + s * 8 + lg);
        cp16(bStg[s] + bDst0, gB + (size_t)(s * 64 + lrow) * RWB + lg);
        cp16(bStg[s] + bDst1, gB + (size_t)(s * 64 + lrow + 32) * RWB + lg);
        CP_COMMIT();
    }

    const int arow = wm0 + (lane & 15);
    const u32 aoff = (u32)(arow * 9 + (lane >> 4)) * 16;
    // trans-B addressing: row (k=v) lane part, col (n=h) granule
    const int trow = (lane & 7) + ((lane >> 3) & 1) * 8;
    const int tcolg = (wn0 >> 3) + (lane >> 4);

    for (int c = 0; c < NCH; c++) {
        CP_WAIT(AVS - 2);
        __syncthreads();

        int cn = c + AVS - 1;
        if (cn < NCH) {
            int s = cn & (AVS - 1);
            cp16(aStg[s] + aDst, gA + (size_t)lrow * RWA + cn * 8 + lg);
            cp16(bStg[s] + bDst0, gB + (size_t)(cn * 64 + lrow) * RWB + lg);
            cp16(bStg[s] + bDst1, gB + (size_t)(cn * 64 + lrow + 32) * RWB + lg);
        }
        CP_COMMIT();

        const u32 bA = aStg[c & (AVS - 1)];
        const u32 bBs = bStg[c & (AVS - 1)];
#pragma unroll
        for (int kb = 0; kb < 4; kb++) {
            u32 a[4], r0, r1, r2, r3;
            ldsm4(a[0], a[1], a[2], a[3], bA + aoff + (u32)(kb * 2) * 16);
            u32 bd = (u32)((kb * 16 + trow) * 9 + tcolg) * 16;
            ldsm4t(r0, r1, r2, r3, bBs + bd);
            u32 bb0[2] = {r0, r1};
            u32 bb1[2] = {r2, r3};
            mma_fp(dacc[0], a, bb0);
            mma_fp(dacc[1], a, bb1);
        }
    }

    const int g = lane >> 2;
    const int t = lane & 3;
#pragma unroll
    for (int nf = 0; nf < 2; nf++) {
        int row = m0 + wm0 + g;
        int col = n0 + wn0 + nf * 8 + t * 2;
        float2 v0, v1;
        v0.x = dacc[nf][0]; v0.y = dacc[nf][1];
        v1.x = dacc[nf][2]; v1.y = dacc[nf][3];
        *(float2*)(out + (size_t)(b * QQ + row) * HH + col) = v0;
        *(float2*)(out + (size_t)(b * QQ + row + 8) * HH + col) = v1;
    }
}

// ---------------------------------------------------------------------------
extern "C" void kernel_launch(void* const* d_in, const int* in_sizes, int n_in,
                              void* d_out, int out_size)
{
    const float* queries = (const float*)d_in[0];
    const float* values  = (const float*)d_in[1];
    const float* w1      = (const float*)d_in[2];
    const float* w2      = (const float*)d_in[3];
    const float* vvec    = (const float*)d_in[4];
    float* out = (float*)d_out;

    const int smemB = (2592 + NQMAX * VV + 1792) * 4;  // 74,880 B
    cudaFuncSetAttribute(score_kernel,
                         cudaFuncAttributeMaxDynamicSharedMemorySize, smemB);

    conv_kernel<<<1184, 256>>>(queries, values, w1, w2);
    proj_tc_kernel<<<144, 256>>>();
    score_kernel<<<SCORE_GRID, 256, smemB>>>(vvec);
    av_mma_kernel<<<dim3(HH / 64, QQ / 32, BB), 256>>>(out);
}